// round 1
// baseline (speedup 1.0000x reference)
#include <cuda_runtime.h>
#include <cuda_bf16.h>
#include <cstddef>

// Enframe: out[bc, 2048*? ...] — precisely:
//   x: (8, 2, 480000) f32  -> flatten bc = b*2+c in [0,16)
//   out: (8, 4096, 934) f32, out[b, c*2048 + k, t] = x[b, c, t*512 + k]
// Decompose k = 512*q + r  (q in [0,4), r in [0,512)):
//   out[bc, 512*q + r, t] = x[bc, (t+q)*512 + r]
// => transpose of x viewed as [slots=937, 512], written as 4 t-shifted copies.

#define S_LEN   480000
#define T_OUT   934          // (480000 - 2048)/512 + 1
#define SLOTS   937          // max slot needed = 933 + 3 = 936
#define ROWS    2048         // per-channel output rows (C*FL per b = 4096, per bc = 2048)

__global__ __launch_bounds__(256) void enframe_kernel(const float* __restrict__ x,
                                                      float* __restrict__ out) {
    __shared__ float tile[32][33];   // [slot_local][r_local], padded

    const int rt = blockIdx.x;   // r tile:    0..15  (r = rt*32 + rl)
    const int st = blockIdx.y;   // slot tile: 0..29  (s = st*32 + sl)
    const int bc = blockIdx.z;   // 0..15
    const int tx = threadIdx.x;  // 0..31
    const int ty = threadIdx.y;  // 0..7

    const float* __restrict__ xin = x + (size_t)bc * S_LEN;

    // ---- Load phase: coalesced along r (tx), rows = slots ----
    const int r_load = rt * 32 + tx;
#pragma unroll
    for (int i = 0; i < 4; ++i) {
        const int sl = ty + i * 8;
        const int s  = st * 32 + sl;
        float v = 0.0f;
        if (s < SLOTS) {
            // pos = s*512 + r <= 936*512 + 511 = 479743 < 480000, always in-bounds
            v = xin[(size_t)s * 512 + r_load];
        }
        tile[sl][tx] = v;
    }
    __syncthreads();

    // ---- Write phase: lane (tx) = slot -> t dimension, coalesced stores ----
    float* __restrict__ outb = out + (size_t)bc * ROWS * T_OUT;
    const int s_lane = st * 32 + tx;   // global slot for this lane

#pragma unroll
    for (int q = 0; q < 4; ++q) {
        const int t = s_lane - q;
        const bool ok = (t >= 0) && (t < T_OUT);
#pragma unroll
        for (int i = 0; i < 4; ++i) {
            const int rl = ty + i * 8;
            const int r  = rt * 32 + rl;
            const float v = tile[tx][rl];   // banks (33*tx + rl) % 32: conflict-free
            if (ok) {
                outb[(size_t)(q * 512 + r) * T_OUT + t] = v;
            }
        }
    }
}

extern "C" void kernel_launch(void* const* d_in, const int* in_sizes, int n_in,
                              void* d_out, int out_size) {
    const float* x = (const float*)d_in[0];
    float* out = (float*)d_out;

    dim3 block(32, 8, 1);
    dim3 grid(16, 30, 16);   // (r tiles, slot tiles, bc)
    enframe_kernel<<<grid, block>>>(x, out);
}

// round 2
// speedup vs baseline: 1.0330x; 1.0330x over previous
#include <cuda_runtime.h>
#include <cuda_bf16.h>
#include <cstddef>

// Enframe: x (8,2,480000) f32 -> out (8,4096,934) f32
//   out[b, c*2048 + k, t] = x[b, c, t*512 + k]
// Decompose k = 512*q + r (q in [0,4), r in [0,512)):
//   out[bc, q*512 + r, t] = x[bc, (t+q)*512 + r],  bc = b*2 + c
// => 512-column transpose of x viewed as [slots, 512], emitted 4x with t-shifts.

#define S_LEN   480000
#define T_OUT   934          // (480000 - 2048)/512 + 1
#define SLOTS   937          // max slot = 933 + 3 = 936
#define ROWS    2048         // per-bc output rows
#define QSTRIDE (512 * T_OUT)

__global__ __launch_bounds__(256) void enframe_kernel(const float4* __restrict__ x4,
                                                      float* __restrict__ out) {
    // tile: 32 slots x 64 r  (16 float4 columns), +1 f4 pad for conflict-free access
    __shared__ float4 tile[32][17];

    const int rt = blockIdx.x;   // 0..7   r base = rt*64
    const int st = blockIdx.y;   // 0..29  slot base = st*32
    const int bc = blockIdx.z;   // 0..15
    const int tx = threadIdx.x;  // 0..31
    const int ty = threadIdx.y;  // 0..7

    const float4* __restrict__ xin = x4 + (size_t)bc * (S_LEN / 4);

    // ---- Load phase: LDG.128 coalesced along r, STS.128 into tile ----
    const int c_load = tx & 15;        // float4 column within tile
    const int half   = tx >> 4;        // 2 slot-rows per warp pass
#pragma unroll
    for (int i = 0; i < 2; ++i) {
        const int sl = (ty + 8 * i) * 2 + half;   // 0..31
        const int s  = st * 32 + sl;
        float4 v = make_float4(0.f, 0.f, 0.f, 0.f);
        if (s < SLOTS) {
            // float4 index: s*128 + rt*16 + c_load  (always in-bounds for s < SLOTS)
            v = xin[(size_t)s * 128 + rt * 16 + c_load];
        }
        tile[sl][c_load] = v;
    }
    __syncthreads();

    // ---- Store phase: lane (tx) = slot -> t, coalesced STG.32 along t ----
    float* __restrict__ outb = out + (size_t)bc * ROWS * T_OUT;
    const int t0 = st * 32 + tx;     // slot handled by this lane

    const bool interior = (st != 0) && (st != 29);

    if (interior) {
#pragma unroll
        for (int j = 0; j < 2; ++j) {
            const int c = ty + 8 * j;            // float4 column 0..15
            const float4 v = tile[tx][c];        // LDS.128, conflict-free
            const int rbase = rt * 64 + 4 * c;
#pragma unroll
            for (int q = 0; q < 4; ++q) {
                float* o = outb + (size_t)q * QSTRIDE + (size_t)rbase * T_OUT + (t0 - q);
                __stcs(o + 0 * T_OUT, v.x);
                __stcs(o + 1 * T_OUT, v.y);
                __stcs(o + 2 * T_OUT, v.z);
                __stcs(o + 3 * T_OUT, v.w);
            }
        }
    } else {
#pragma unroll
        for (int j = 0; j < 2; ++j) {
            const int c = ty + 8 * j;
            const float4 v = tile[tx][c];
            const int rbase = rt * 64 + 4 * c;
#pragma unroll
            for (int q = 0; q < 4; ++q) {
                const int t = t0 - q;
                if (t >= 0 && t < T_OUT) {
                    float* o = outb + (size_t)q * QSTRIDE + (size_t)rbase * T_OUT + t;
                    __stcs(o + 0 * T_OUT, v.x);
                    __stcs(o + 1 * T_OUT, v.y);
                    __stcs(o + 2 * T_OUT, v.z);
                    __stcs(o + 3 * T_OUT, v.w);
                }
            }
        }
    }
}

extern "C" void kernel_launch(void* const* d_in, const int* in_sizes, int n_in,
                              void* d_out, int out_size) {
    const float4* x = (const float4*)d_in[0];
    float* out = (float*)d_out;

    dim3 block(32, 8, 1);
    dim3 grid(8, 30, 16);   // (r tiles of 64, slot tiles of 32, bc)
    enframe_kernel<<<grid, block>>>(x, out);
}

// round 3
// speedup vs baseline: 1.3669x; 1.3232x over previous
#include <cuda_runtime.h>
#include <cuda_bf16.h>
#include <cstddef>

// Enframe: x (8,2,480000) f32 -> out (8,4096,934) f32
//   out[b, c*2048 + k, t] = x[b, c, t*512 + k]
// Decompose k = 512*q + r (q in [0,4), r in [0,512)), bc = b*2+c:
//   out[bc, q*512 + r, t] = x[bc, (t+q)*512 + r]
// => transpose of x viewed as [slots, 512]; block covers 128 t x 32 r,
//    stores float2 along t (rows are 8B-aligned: 934*4 = 3736 % 8 == 0).

#define S_LEN     480000
#define T_OUT     934          // (480000 - 2048)/512 + 1
#define SLOTS     937          // max slot = 933 + 3 = 936
#define ROWS      2048         // per-bc output rows
#define R_PAD     33
#define T_TILE    128
#define SLOT_NEED 131          // t range + q shift (3) + pair (+1) -> 128+3 = 131 rows

__global__ __launch_bounds__(256) void enframe_kernel(const float4* __restrict__ x4,
                                                      float* __restrict__ out) {
    __shared__ float tile[SLOT_NEED * R_PAD];   // 131*33*4 = 17292 B

    const int rt = blockIdx.x;   // 0..15  r base = rt*32
    const int tt = blockIdx.y;   // 0..7   t base = tt*128
    const int bc = blockIdx.z;   // 0..15
    const int tx = threadIdx.x;  // 0..31
    const int ty = threadIdx.y;  // 0..7

    const int tb = tt * T_TILE;
    const float4* __restrict__ xin = x4 + (size_t)bc * (S_LEN / 4);

    // ---- Load phase: LDG.128, each warp = 4 slot-rows x 8 float4 columns ----
    const int c      = tx & 7;          // float4 column 0..7 (r = rt*32 + 4c..)
    const int rowoff = tx >> 3;         // 0..3
    const bool interior = (tt < 7);     // t-tiles 0..6: no guards anywhere

    if (interior) {
#pragma unroll
        for (int p = 0; p < 5; ++p) {
            const int row = p * 32 + ty * 4 + rowoff;
            if (row < SLOT_NEED) {
                const float4 v = xin[(size_t)(tb + row) * 128 + rt * 8 + c];
                const int base = row * R_PAD + 4 * c;
                tile[base + 0] = v.x; tile[base + 1] = v.y;
                tile[base + 2] = v.z; tile[base + 3] = v.w;
            }
        }
    } else {
#pragma unroll
        for (int p = 0; p < 5; ++p) {
            const int row = p * 32 + ty * 4 + rowoff;
            if (row < SLOT_NEED) {
                const int s = tb + row;
                float4 v = make_float4(0.f, 0.f, 0.f, 0.f);
                if (s < SLOTS) v = xin[(size_t)s * 128 + rt * 8 + c];
                const int base = row * R_PAD + 4 * c;
                tile[base + 0] = v.x; tile[base + 1] = v.y;
                tile[base + 2] = v.z; tile[base + 3] = v.w;
            }
        }
    }
    __syncthreads();

    // ---- Store phase: warp ty owns (q = ty>>1, half = ty&1); lane = t pair ----
    const int q    = ty >> 1;
    const int half = ty & 1;
    const int t    = tb + half * 64 + 2 * tx;      // even t; pair (t, t+1)
    const int row  = half * 64 + 2 * tx + q;       // slot-row for t
    const float* __restrict__ src = &tile[row * R_PAD];

    float* __restrict__ o = out + (size_t)bc * ROWS * T_OUT
                                + (size_t)(q * 512 + rt * 32) * T_OUT + t;

    if (interior || t < T_OUT) {     // t even, T_OUT even -> pair fully valid
#pragma unroll
        for (int rl = 0; rl < 32; ++rl) {
            float2 v;
            v.x = src[rl];            // tile[row][rl]
            v.y = src[R_PAD + rl];    // tile[row+1][rl]  (slot s+1 -> t+1)
            *(float2*)o = v;          // STG.64, 8B-aligned
            o += T_OUT;
        }
    }
}

extern "C" void kernel_launch(void* const* d_in, const int* in_sizes, int n_in,
                              void* d_out, int out_size) {
    const float4* x = (const float4*)d_in[0];
    float* out = (float*)d_out;

    dim3 block(32, 8, 1);
    dim3 grid(16, 8, 16);   // (r tiles of 32, t tiles of 128, bc)
    enframe_kernel<<<grid, block>>>(x, out);
}